// round 3
// baseline (speedup 1.0000x reference)
#include <cuda_runtime.h>
#include <math.h>

#define B 32
#define D 256
#define NN 10000
#define H_ATTN 500
#define H_MLP 1024
#define ALPHA 0.2f

// ---------------- scratch (device globals; no allocations) ----------------
__device__ float g_state[B*D];
__device__ float g_gate[B*D];
__device__ float g_t1[B*H_MLP];
__device__ float g_gf[B*D];
__device__ float g_q[D];
__device__ float g_u[B*D];
__device__ float g_awlog[B*NN];
__device__ float g_aw[B*NN];
__device__ float g_c0;

__device__ __forceinline__ float sigmoidf_(float x){ return 1.f/(1.f+__expf(-x)); }

// ============ KA: blocks [0,32): state/gate/zero-u | [32,160): t1 | [160,192): q,c0
__global__ void KA(const float* __restrict__ ehr,  const float* __restrict__ path,
                   const float* __restrict__ W_pf, const float* __restrict__ b_pf,
                   const float* __restrict__ W_gate,const float* __restrict__ b_gate,
                   const float* __restrict__ W1,   const float* __restrict__ b1,
                   const float* __restrict__ W_s1, const float* __restrict__ W_s2,
                   const float* __restrict__ b_s1, const float* __restrict__ b_s2){
  int bid = blockIdx.x, t = threadIdx.x;
  if (bid < 32){
    __shared__ float se[D], sp[D];
    int b = bid, d = t;
    se[d] = ehr[b*D+d]; sp[d] = path[b*D+d];
    __syncthreads();
    float acc = 0.f, ag = 0.f;
    #pragma unroll 4
    for (int k = 0; k < D; k++){
      float e = se[k], p = sp[k];
      const float* w = W_pf + k*D + d;
      acc += p*w[0]        + e*w[1*D*D]    + (e*p)*w[2*D*D]
           + (e-p)*w[3*D*D]+ (p-e)*w[4*D*D]+ (e+p)*w[5*D*D];
      ag  += e * W_gate[k*D + d];
    }
    g_state[b*D+d] = tanhf(acc + b_pf[d]);
    g_gate[b*D+d]  = sigmoidf_(ag + b_gate[d]);
    g_u[b*D+d]     = 0.f;
  } else if (bid < 160){
    int idx = bid - 32;
    int b = idx >> 2, j = (idx & 3)*256 + t;
    __shared__ float se[D];
    se[t] = ehr[b*D+t];
    __syncthreads();
    float a = 0.f;
    #pragma unroll 4
    for (int k = 0; k < D; k++) a += se[k]*W1[k*H_MLP + j];
    g_t1[b*H_MLP + j] = fmaxf(a + b1[j], 0.f);
  } else {
    int qb = bid - 160;                 // 0..31
    int w = t >> 5, lane = t & 31;
    int d = qb*8 + w;                   // 8 d per block, one warp each
    const float* row = W_s1 + d*H_ATTN;
    float s = 0.f;
    for (int h = lane; h < H_ATTN; h += 32) s += row[h]*W_s2[h];   // coalesced
    #pragma unroll
    for (int o = 16; o > 0; o >>= 1) s += __shfl_down_sync(0xffffffffu, s, o);
    if (lane == 0) g_q[d] = s;
    if (qb == 0 && w == 0){
      float c = 0.f;
      for (int h = lane; h < H_ATTN; h += 32) c += b_s1[h]*W_s2[h];
      #pragma unroll
      for (int o = 16; o > 0; o >>= 1) c += __shfl_down_sync(0xffffffffu, c, o);
      if (lane == 0) g_c0 = c + b_s2[0];
    }
  }
}

// ============ KB: blocks [0,32): gf | [32,189): awlog (64 n per block)
__global__ void KB(const float* __restrict__ W2, const float* __restrict__ b2,
                   const float* __restrict__ emb){
  int bid = blockIdx.x, t = threadIdx.x;          // 256 threads
  if (bid < 32){
    __shared__ float st[H_MLP];
    int b = bid;
    for (int i = t; i < H_MLP; i += 256) st[i] = g_t1[b*H_MLP + i];
    __syncthreads();
    float a = 0.f;
    #pragma unroll 4
    for (int k = 0; k < H_MLP; k++) a += st[k]*W2[k*D + t];
    g_gf[b*D + t] = fmaxf(a + b2[t], 0.f);
  } else {
    int n0 = (bid - 32)*64;
    __shared__ float semb[64][33];
    __shared__ float ssq[32][33];
    int nloc = t & 63, bq = t >> 6;               // bq 0..3 -> 8 b each
    float acc[8];
    #pragma unroll
    for (int i = 0; i < 8; i++) acc[i] = 0.f;
    for (int dc = 0; dc < 8; dc++){
      for (int i = t; i < 64*32; i += 256){
        int r = i >> 5, c = i & 31; int n = n0 + r;
        semb[r][c] = (n < NN) ? emb[n*D + dc*32 + c] : 0.f;
      }
      for (int i = t; i < 32*32; i += 256){
        int b = i >> 5, c = i & 31;
        ssq[b][c] = g_state[b*D + dc*32 + c]*g_q[dc*32 + c];   // sq on the fly
      }
      __syncthreads();
      #pragma unroll
      for (int c = 0; c < 32; c++){
        float e = semb[nloc][c];
        #pragma unroll
        for (int bb = 0; bb < 8; bb++) acc[bb] += e*ssq[bq*8 + bb][c];
      }
      __syncthreads();
    }
    int n = n0 + nloc;
    if (n < NN){
      float c0 = g_c0;
      #pragma unroll
      for (int bb = 0; bb < 8; bb++) g_awlog[(bq*8 + bb)*NN + n] = acc[bb] + c0;
    }
  }
}

// ============ KC: masked softmax (logits MULTIPLIED by mask, per reference)
__global__ void KC(const float* __restrict__ asp){
  int b = blockIdx.x, t = threadIdx.x;            // 512 threads
  __shared__ float red[512];
  const float* al = g_awlog + b*NN;
  const float* m  = asp + b*NN;
  float mx = -1e30f;
  for (int n = t; n < NN; n += 512) mx = fmaxf(mx, al[n]*m[n]);
  red[t] = mx; __syncthreads();
  for (int s = 256; s > 0; s >>= 1){ if (t < s) red[t] = fmaxf(red[t], red[t+s]); __syncthreads(); }
  mx = red[0]; __syncthreads();
  float se = 0.f;
  for (int n = t; n < NN; n += 512) se += __expf(al[n]*m[n] - mx);
  red[t] = se; __syncthreads();
  for (int s = 256; s > 0; s >>= 1){ if (t < s) red[t] += red[t+s]; __syncthreads(); }
  float inv = 1.f/red[0];
  for (int n = t; n < NN; n += 512) g_aw[b*NN + n] = __expf(al[n]*m[n] - mx)*inv;
}

// ============ KD: u[b,:] += aw[b, nchunk] @ emb[nchunk,:]  (157 blocks x 64 n)
__global__ void KD(const float* __restrict__ emb){
  __shared__ float saw[32][64];
  __shared__ float semb[64][32];
  int t = threadIdx.x;                            // 256
  int n0 = blockIdx.x*64;
  for (int i = t; i < 32*64; i += 256){
    int b = i >> 6, j = i & 63; int n = n0 + j;
    saw[b][j] = (n < NN) ? g_aw[b*NN + n] : 0.f;
  }
  __syncthreads();
  int dl = t & 31, g = t >> 5;                    // 8 groups x 4 b
  for (int dc = 0; dc < 8; dc++){
    for (int i = t; i < 64*32; i += 256){
      int r = i >> 5, c = i & 31; int n = n0 + r;
      semb[r][c] = (n < NN) ? emb[n*D + dc*32 + c] : 0.f;
    }
    __syncthreads();
    #pragma unroll
    for (int bb = 0; bb < 4; bb++){
      int b = g*4 + bb;
      float a = 0.f;
      #pragma unroll
      for (int j = 0; j < 64; j++) a += saw[b][j]*semb[j][dl];
      atomicAdd(&g_u[b*D + dc*32 + dl], a);
    }
    __syncthreads();
  }
}

// ============ KE: fused highway + dual GEMV + blend  (157 blocks x 128 thr, 64 n)
__global__ void KE(const float* __restrict__ ehr, const float* __restrict__ asp,
                   const float* __restrict__ lvl,
                   const float* __restrict__ W_gl, const float* __restrict__ b_gl,
                   const float* __restrict__ W_lay,const float* __restrict__ b_lay,
                   float* __restrict__ out){
  __shared__ float shw[32][64];
  __shared__ float sgf[32][64];
  __shared__ float sred[64][33];
  int t = threadIdx.x;                            // 128
  int n0 = blockIdx.x*64;
  int nloc = t & 63, half = t >> 6;
  int n = n0 + nloc;
  float accL[32], accG[32];
  #pragma unroll
  for (int b = 0; b < 32; b++){ accL[b] = 0.f; accG[b] = 0.f; }
  for (int dc = 0; dc < 4; dc++){
    for (int i = t; i < 32*64; i += 128){         // stage highway (computed inline) + gf
      int b = i >> 6, c = i & 63; int d = dc*64 + c;
      float gt = g_gate[b*D + d];
      float br = g_state[b*D + d]*g_u[b*D + d];
      shw[b][c] = br*(1.f - gt) + ehr[b*D + d]*gt;
      sgf[b][c] = g_gf[b*D + d];
    }
    __syncthreads();
    if (n < NN){
      #pragma unroll 4
      for (int cc = 0; cc < 32; cc++){
        int c = half*32 + cc;
        int d = dc*64 + c;
        float wl = W_lay[d*NN + n];
        float wg = W_gl [d*NN + n];
        #pragma unroll
        for (int b = 0; b < 32; b++){
          accL[b] += shw[b][c]*wl;
          accG[b] += sgf[b][c]*wg;
        }
      }
    }
    __syncthreads();
  }
  // combine d-halves via smem
  if (half == 1){
    #pragma unroll
    for (int b = 0; b < 32; b++) sred[nloc][b] = accL[b];
  }
  __syncthreads();
  if (half == 0){
    #pragma unroll
    for (int b = 0; b < 32; b++) accL[b] += sred[nloc][b];
  }
  __syncthreads();
  if (half == 1){
    #pragma unroll
    for (int b = 0; b < 32; b++) sred[nloc][b] = accG[b];
  }
  __syncthreads();
  if (half == 0 && n < NN){
    float bl = b_lay[n], bg = b_gl[n], lm = lvl[n];
    #pragma unroll
    for (int b = 0; b < 32; b++){
      float ll = sigmoidf_(accL[b] + bl);
      float lg = sigmoidf_(accG[b] + sred[nloc][b] + bg);
      out[b*NN + n] = ALPHA*ll*asp[b*NN + n] + (1.f - ALPHA)*lg*lm;
    }
  }
}

// ---------------- launch ----------------
extern "C" void kernel_launch(void* const* d_in, const int* in_sizes, int n_in,
                              void* d_out, int out_size){
  const float* ehr    = (const float*)d_in[0];
  const float* path   = (const float*)d_in[1];
  const float* asp    = (const float*)d_in[2];
  const float* lvl    = (const float*)d_in[3];
  const float* emb    = (const float*)d_in[4];
  const float* W_pf   = (const float*)d_in[5];
  const float* b_pf   = (const float*)d_in[6];
  const float* W_s1   = (const float*)d_in[7];
  const float* b_s1   = (const float*)d_in[8];
  const float* W_s2   = (const float*)d_in[9];
  const float* b_s2   = (const float*)d_in[10];
  const float* W_gate = (const float*)d_in[11];
  const float* b_gate = (const float*)d_in[12];
  const float* W1     = (const float*)d_in[13];
  const float* b1     = (const float*)d_in[14];
  const float* W2     = (const float*)d_in[15];
  const float* b2     = (const float*)d_in[16];
  const float* W_gl   = (const float*)d_in[17];
  const float* b_gl   = (const float*)d_in[18];
  const float* W_lay  = (const float*)d_in[19];
  const float* b_lay  = (const float*)d_in[20];
  float* out = (float*)d_out;

  KA<<<192, 256>>>(ehr, path, W_pf, b_pf, W_gate, b_gate, W1, b1, W_s1, W_s2, b_s1, b_s2);
  KB<<<189, 256>>>(W2, b2, emb);
  KC<<<32, 512>>>(asp);
  KD<<<157, 256>>>(emb);
  KE<<<157, 128>>>(ehr, asp, lvl, W_gl, b_gl, W_lay, b_lay, out);
}

// round 4
// speedup vs baseline: 1.2488x; 1.2488x over previous
#include <cuda_runtime.h>
#include <math.h>

#define B 32
#define D 256
#define NN 10000
#define H_ATTN 500
#define H_MLP 1024
#define ALPHA 0.2f

// ---------------- scratch (device globals; no allocations) ----------------
__device__ float g_state[B*D];
__device__ float g_gate[B*D];
__device__ float g_t1[B*H_MLP];
__device__ float g_gf[B*D];
__device__ float g_q[D];
__device__ float g_u[B*D];       // unnormalized  sum_n w * emb
__device__ float g_S[B];         // sum_n w
__device__ float g_c0;

__device__ __forceinline__ float sigmoidf_(float x){ return 1.f/(1.f+__expf(-x)); }

// ============ KA: [0,32): state/gate + zero u,S | [32,160): t1 | [160,192): q,c0
__global__ void KA(const float* __restrict__ ehr,  const float* __restrict__ path,
                   const float* __restrict__ W_pf, const float* __restrict__ b_pf,
                   const float* __restrict__ W_gate,const float* __restrict__ b_gate,
                   const float* __restrict__ W1,   const float* __restrict__ b1,
                   const float* __restrict__ W_s1, const float* __restrict__ W_s2,
                   const float* __restrict__ b_s1, const float* __restrict__ b_s2){
  int bid = blockIdx.x, t = threadIdx.x;
  if (bid < 32){
    __shared__ float se[D], sp[D];
    int b = bid, d = t;
    se[d] = ehr[b*D+d]; sp[d] = path[b*D+d];
    __syncthreads();
    float acc = 0.f, ag = 0.f;
    #pragma unroll 4
    for (int k = 0; k < D; k++){
      float e = se[k], p = sp[k];
      const float* w = W_pf + k*D + d;
      acc += p*w[0]        + e*w[1*D*D]    + (e*p)*w[2*D*D]
           + (e-p)*w[3*D*D]+ (p-e)*w[4*D*D]+ (e+p)*w[5*D*D];
      ag  += e * W_gate[k*D + d];
    }
    g_state[b*D+d] = tanhf(acc + b_pf[d]);
    g_gate[b*D+d]  = sigmoidf_(ag + b_gate[d]);
    g_u[b*D+d]     = 0.f;
    if (bid == 0 && t < B) g_S[t] = 0.f;
  } else if (bid < 160){
    int idx = bid - 32;
    int b = idx >> 2, j = (idx & 3)*256 + t;
    __shared__ float se[D];
    se[t] = ehr[b*D+t];
    __syncthreads();
    float a = 0.f;
    #pragma unroll 4
    for (int k = 0; k < D; k++) a += se[k]*W1[k*H_MLP + j];
    g_t1[b*H_MLP + j] = fmaxf(a + b1[j], 0.f);
  } else {
    int qb = bid - 160;                 // 0..31
    int w = t >> 5, lane = t & 31;
    int d = qb*8 + w;
    const float* row = W_s1 + d*H_ATTN;
    float s = 0.f;
    for (int h = lane; h < H_ATTN; h += 32) s += row[h]*W_s2[h];
    #pragma unroll
    for (int o = 16; o > 0; o >>= 1) s += __shfl_down_sync(0xffffffffu, s, o);
    if (lane == 0) g_q[d] = s;
    if (qb == 0 && w == 0){
      float c = 0.f;
      for (int h = lane; h < H_ATTN; h += 32) c += b_s1[h]*W_s2[h];
      #pragma unroll
      for (int o = 16; o > 0; o >>= 1) c += __shfl_down_sync(0xffffffffu, c, o);
      if (lane == 0) g_c0 = c + b_s2[0];
    }
  }
}

// ============ KB: [0,32): gf | [32,345): fused attention (32 n per block)
//   pass1: logit[b,n] = emb[n,:].sq[b,:] + c0   (emb tile resident in smem)
//   w = exp(logit*mask)  (max-shift cancels; logits ~1e-3, no overflow)
//   pass2: u_raw += w.emb  (atomics);  S += sum w
__global__ void KB(const float* __restrict__ W2, const float* __restrict__ b2,
                   const float* __restrict__ emb, const float* __restrict__ asp){
  __shared__ float semb[32][257];
  __shared__ float ssq[32][33];
  __shared__ float sw[32][33];
  __shared__ float sS[32];
  __shared__ float st[H_MLP];
  int bid = blockIdx.x, t = threadIdx.x;          // 256 threads
  if (bid < 32){
    int b = bid;
    for (int i = t; i < H_MLP; i += 256) st[i] = g_t1[b*H_MLP + i];
    __syncthreads();
    float a = 0.f;
    #pragma unroll 4
    for (int k = 0; k < H_MLP; k++) a += st[k]*W2[k*D + t];
    g_gf[b*D + t] = fmaxf(a + b2[t], 0.f);
    return;
  }
  int n0 = (bid - 32)*32;
  // load emb tile [32 n][256 d], coalesced
  #pragma unroll
  for (int i = t; i < 32*256; i += 256){
    int r = i >> 8, c = i & 255; int n = n0 + r;
    semb[r][c] = (n < NN) ? emb[n*D + c] : 0.f;
  }
  if (t < 32) sS[t] = 0.f;

  // ---- pass 1: logits ----
  int nloc = t & 31, bq = t >> 5;                 // 8 warps, 4 b each
  float acc[4];
  #pragma unroll
  for (int i = 0; i < 4; i++) acc[i] = 0.f;
  for (int dc = 0; dc < 8; dc++){
    __syncthreads();
    for (int i = t; i < 32*32; i += 256){
      int b = i >> 5, c = i & 31;
      ssq[b][c] = g_state[b*D + dc*32 + c]*g_q[dc*32 + c];
    }
    __syncthreads();
    #pragma unroll
    for (int c = 0; c < 32; c++){
      float e = semb[nloc][dc*32 + c];
      #pragma unroll
      for (int bb = 0; bb < 4; bb++) acc[bb] += e*ssq[bq*4 + bb][c];
    }
  }
  // ---- exp + block-local S ----
  int n = n0 + nloc;
  float c0 = g_c0;
  #pragma unroll
  for (int bb = 0; bb < 4; bb++){
    int b = bq*4 + bb;
    float w = 0.f;
    if (n < NN) w = __expf((acc[bb] + c0)*asp[b*NN + n]);
    sw[b][nloc] = w;
    float s = w;
    #pragma unroll
    for (int o = 16; o > 0; o >>= 1) s += __shfl_down_sync(0xffffffffu, s, o);
    if (nloc == 0) atomicAdd(&sS[b], s);
  }
  __syncthreads();

  // ---- pass 2: u_raw += w . emb ----
  int dl = t & 31, g = t >> 5;                    // 8 groups, 4 b each
  for (int dc = 0; dc < 8; dc++){
    float a[4];
    #pragma unroll
    for (int i = 0; i < 4; i++) a[i] = 0.f;
    #pragma unroll
    for (int j = 0; j < 32; j++){
      float e = semb[j][dc*32 + dl];
      #pragma unroll
      for (int bb = 0; bb < 4; bb++) a[bb] += sw[g*4 + bb][j]*e;
    }
    #pragma unroll
    for (int bb = 0; bb < 4; bb++)
      atomicAdd(&g_u[(g*4 + bb)*D + dc*32 + dl], a[bb]);
  }
  if (t < 32) atomicAdd(&g_S[t], sS[t]);
}

// ============ KE: fused normalize + highway + dual GEMV + blend
// grid 157 x 512 threads, 64 n per block; thread = (nloc, 4 b)
__global__ void KE(const float* __restrict__ ehr, const float* __restrict__ asp,
                   const float* __restrict__ lvl,
                   const float* __restrict__ W_gl, const float* __restrict__ b_gl,
                   const float* __restrict__ W_lay,const float* __restrict__ b_lay,
                   float* __restrict__ out){
  __shared__ float2 sv[32][130];                  // {highway, gf} for half of d
  int t = threadIdx.x;                            // 512
  int nloc = t & 63, bq = t >> 6;                 // 8 groups x 4 b
  int n = blockIdx.x*64 + nloc;
  float accL[4], accG[4];
  #pragma unroll
  for (int i = 0; i < 4; i++){ accL[i] = 0.f; accG[i] = 0.f; }
  for (int h = 0; h < 2; h++){
    for (int i = t; i < 32*128; i += 512){
      int b = i >> 7, c = i & 127; int d = h*128 + c;
      float gt = g_gate[b*D + d];
      float u  = g_state[b*D + d]*(g_u[b*D + d]/g_S[b]);
      float hw = u*(1.f - gt) + ehr[b*D + d]*gt;
      sv[b][c] = make_float2(hw, g_gf[b*D + d]);
    }
    __syncthreads();
    if (n < NN){
      #pragma unroll 4
      for (int c = 0; c < 128; c++){
        int d = h*128 + c;
        float wl = W_lay[d*NN + n];
        float wg = W_gl [d*NN + n];
        #pragma unroll
        for (int bb = 0; bb < 4; bb++){
          float2 v = sv[bq*4 + bb][c];
          accL[bb] += v.x*wl;
          accG[bb] += v.y*wg;
        }
      }
    }
    __syncthreads();
  }
  if (n < NN){
    float bl = b_lay[n], bg = b_gl[n], lm = lvl[n];
    #pragma unroll
    for (int bb = 0; bb < 4; bb++){
      int b = bq*4 + bb;
      float ll = sigmoidf_(accL[bb] + bl);
      float lg = sigmoidf_(accG[bb] + bg);
      out[b*NN + n] = ALPHA*ll*asp[b*NN + n] + (1.f - ALPHA)*lg*lm;
    }
  }
}

// ---------------- launch ----------------
extern "C" void kernel_launch(void* const* d_in, const int* in_sizes, int n_in,
                              void* d_out, int out_size){
  const float* ehr    = (const float*)d_in[0];
  const float* path   = (const float*)d_in[1];
  const float* asp    = (const float*)d_in[2];
  const float* lvl    = (const float*)d_in[3];
  const float* emb    = (const float*)d_in[4];
  const float* W_pf   = (const float*)d_in[5];
  const float* b_pf   = (const float*)d_in[6];
  const float* W_s1   = (const float*)d_in[7];
  const float* b_s1   = (const float*)d_in[8];
  const float* W_s2   = (const float*)d_in[9];
  const float* b_s2   = (const float*)d_in[10];
  const float* W_gate = (const float*)d_in[11];
  const float* b_gate = (const float*)d_in[12];
  const float* W1     = (const float*)d_in[13];
  const float* b1     = (const float*)d_in[14];
  const float* W2     = (const float*)d_in[15];
  const float* b2     = (const float*)d_in[16];
  const float* W_gl   = (const float*)d_in[17];
  const float* b_gl   = (const float*)d_in[18];
  const float* W_lay  = (const float*)d_in[19];
  const float* b_lay  = (const float*)d_in[20];
  float* out = (float*)d_out;

  KA<<<192, 256>>>(ehr, path, W_pf, b_pf, W_gate, b_gate, W1, b1, W_s1, W_s2, b_s1, b_s2);
  KB<<<345, 256>>>(W2, b2, emb, asp);
  KE<<<157, 512>>>(ehr, asp, lvl, W_gl, b_gl, W_lay, b_lay, out);
}

// round 5
// speedup vs baseline: 1.5929x; 1.2756x over previous
#include <cuda_runtime.h>
#include <math.h>

#define B 32
#define D 256
#define NN 10000
#define H_ATTN 500
#define H_MLP 1024
#define ALPHA 0.2f

// ---------------- scratch (device globals; zero-initialized at load) ------
__device__ float g_acc_state[B*D];   // split-K partials (zeroed after use)
__device__ float g_acc_gate[B*D];
__device__ float g_acc_t1[B*H_MLP];
__device__ float g_state[B*D];
__device__ float g_sq[B*D];          // tanh(state)*q
__device__ float g_gate[B*D];
__device__ float g_t1[B*H_MLP];      // relu'd
__device__ float g_gf[B*D];
__device__ float g_q[D];
__device__ float g_u[B*D];           // unnormalized sum_n w*emb (zeroed after use)
__device__ float g_S[B];             // sum_n w (zeroed after use)
__device__ float g_c0;
__device__ float2 g_hg[B*D];         // {highway, gf}

__device__ __forceinline__ float sigmoidf_(float x){ return 1.f/(1.f+__expf(-x)); }

// ---- split-K GEMM tile: out[b][d0+dd] += sum_{k0<=k<k0+64} sf[b][k-k0]*W[k][d0+dd]
// thread: dq = t&15 (4 consecutive d), bg = t>>4 (2 consecutive b). 8 atomics/thread.
__device__ __forceinline__ void gemm_part(const float* __restrict__ W, int ldw,
                                          int k0, int d0, const float (*sf)[68],
                                          float* __restrict__ outacc, int ldo, int t){
  int dq = t & 15, bg = t >> 4;
  int b0 = bg*2, b1 = b0 + 1;
  const float* Wp = W + (size_t)k0*ldw + d0 + dq*4;
  float4 a0 = make_float4(0.f,0.f,0.f,0.f);
  float4 a1 = make_float4(0.f,0.f,0.f,0.f);
  #pragma unroll 4
  for (int kq = 0; kq < 16; kq++){
    int k = kq*4;
    float4 w0 = *(const float4*)(Wp + (size_t)(k+0)*ldw);
    float4 w1 = *(const float4*)(Wp + (size_t)(k+1)*ldw);
    float4 w2 = *(const float4*)(Wp + (size_t)(k+2)*ldw);
    float4 w3 = *(const float4*)(Wp + (size_t)(k+3)*ldw);
    float4 f0 = *(const float4*)&sf[b0][k];
    float4 f1 = *(const float4*)&sf[b1][k];
    a0.x += f0.x*w0.x + f0.y*w1.x + f0.z*w2.x + f0.w*w3.x;
    a0.y += f0.x*w0.y + f0.y*w1.y + f0.z*w2.y + f0.w*w3.y;
    a0.z += f0.x*w0.z + f0.y*w1.z + f0.z*w2.z + f0.w*w3.z;
    a0.w += f0.x*w0.w + f0.y*w1.w + f0.z*w2.w + f0.w*w3.w;
    a1.x += f1.x*w0.x + f1.y*w1.x + f1.z*w2.x + f1.w*w3.x;
    a1.y += f1.x*w0.y + f1.y*w1.y + f1.z*w2.y + f1.w*w3.y;
    a1.z += f1.x*w0.z + f1.y*w1.z + f1.z*w2.z + f1.w*w3.z;
    a1.w += f1.x*w0.w + f1.y*w1.w + f1.z*w2.w + f1.w*w3.w;
  }
  float* o0 = outacc + b0*ldo + d0 + dq*4;
  float* o1 = outacc + b1*ldo + d0 + dq*4;
  atomicAdd(o0+0, a0.x); atomicAdd(o0+1, a0.y); atomicAdd(o0+2, a0.z); atomicAdd(o0+3, a0.w);
  atomicAdd(o1+0, a1.x); atomicAdd(o1+1, a1.y); atomicAdd(o1+2, a1.z); atomicAdd(o1+3, a1.w);
}

// ============ KA: [0,96) W_pf | [96,112) W_gate | [112,176) W1 | [176,208) q,c0
__global__ void KA(const float* __restrict__ ehr,  const float* __restrict__ path,
                   const float* __restrict__ W_pf,
                   const float* __restrict__ W_gate,
                   const float* __restrict__ W1,
                   const float* __restrict__ W_s1, const float* __restrict__ W_s2,
                   const float* __restrict__ b_s1, const float* __restrict__ b_s2){
  __shared__ float sf[32][68];
  __shared__ float sw2[512];
  int bid = blockIdx.x, t = threadIdx.x;          // 256 threads
  if (bid < 176){
    // select tile
    const float* W; float* outacc; int ldw, k0, d0, seg, kk;
    if (bid < 96){                                // W_pf: 24 k-slices x 4 d-tiles
      int kidx = bid >> 2, dt = bid & 3;
      k0 = kidx*64; d0 = dt*64; seg = k0 >> 8; kk = k0 & 255;
      W = W_pf; ldw = D; outacc = g_acc_state;
    } else if (bid < 112){                        // W_gate: 4 x 4
      int idx = bid - 96;
      k0 = (idx >> 2)*64; d0 = (idx & 3)*64; seg = 1; kk = k0;
      W = W_gate; ldw = D; outacc = g_acc_gate;
    } else {                                      // W1: 4 k-slices x 16 d-tiles
      int idx = bid - 112;
      k0 = (idx >> 4)*64; d0 = (idx & 15)*64; seg = 1; kk = k0;
      W = W1; ldw = H_MLP; outacc = g_acc_t1;
    }
    // stage feature slice [32 b][64 k]
    for (int i = t; i < 512; i += 256){
      int b = i >> 4, j = (i & 15)*4;
      float4 e = *(const float4*)(ehr + b*D + kk + j);
      float4 f;
      if (seg == 1){ f = e; }
      else {
        float4 p = *(const float4*)(path + b*D + kk + j);
        if (seg == 0)      f = p;
        else if (seg == 2) f = make_float4(e.x*p.x, e.y*p.y, e.z*p.z, e.w*p.w);
        else if (seg == 3) f = make_float4(e.x-p.x, e.y-p.y, e.z-p.z, e.w-p.w);
        else if (seg == 4) f = make_float4(p.x-e.x, p.y-e.y, p.z-e.z, p.w-e.w);
        else               f = make_float4(e.x+p.x, e.y+p.y, e.z+p.z, e.w+p.w);
      }
      *(float4*)&sf[b][j] = f;
    }
    __syncthreads();
    int ldo = (bid >= 112 && bid < 176) ? H_MLP : D;
    gemm_part(W, ldw, k0, d0, sf, outacc, ldo, t);
  } else {
    // q[d] = W_s1[d,:].W_s2 ; 32 blocks x 8 warps (warp per d). 500 = 125 float4.
    for (int i = t; i < 125; i += 256)
      *(float4*)&sw2[i*4] = *(const float4*)(W_s2 + i*4);
    __syncthreads();
    int qb = bid - 176, w = t >> 5, lane = t & 31;
    int d = qb*8 + w;
    const float4* row = (const float4*)(W_s1 + d*H_ATTN);   // 2000B row, 16B aligned
    float s = 0.f;
    #pragma unroll
    for (int i = 0; i < 4; i++){
      int idx = lane + i*32;
      if (idx < 125){
        float4 v = row[idx];
        float4 u = *(const float4*)&sw2[idx*4];
        s += v.x*u.x + v.y*u.y + v.z*u.z + v.w*u.w;
      }
    }
    #pragma unroll
    for (int o = 16; o > 0; o >>= 1) s += __shfl_down_sync(0xffffffffu, s, o);
    if (lane == 0) g_q[d] = s;
    if (qb == 0 && w == 0){
      float c = 0.f;
      for (int h = lane; h < H_ATTN; h += 32) c += b_s1[h]*sw2[h];
      #pragma unroll
      for (int o = 16; o > 0; o >>= 1) c += __shfl_down_sync(0xffffffffu, c, o);
      if (lane == 0) g_c0 = c + b_s2[0];
    }
  }
}

// ============ KA2: activations + zero accumulators (32 blocks x 256)
__global__ void KA2(const float* __restrict__ b_pf, const float* __restrict__ b_gate,
                    const float* __restrict__ b1){
  int i = blockIdx.x*256 + threadIdx.x;           // 0..8191 = b*256 + d
  int d = i & 255;
  float st = tanhf(g_acc_state[i] + b_pf[d]);
  g_state[i] = st;
  g_sq[i]    = st * g_q[d];
  g_gate[i]  = sigmoidf_(g_acc_gate[i] + b_gate[d]);
  g_acc_state[i] = 0.f; g_acc_gate[i] = 0.f;
  #pragma unroll
  for (int r = 0; r < 4; r++){
    int j = blockIdx.x*1024 + r*256 + threadIdx.x;  // 0..32767
    int col = j & (H_MLP-1);
    g_t1[j] = fmaxf(g_acc_t1[j] + b1[col], 0.f);
    g_acc_t1[j] = 0.f;
  }
}

// ============ KB: [0,32): gf | [32,345): fused attention (32 n per block)
__global__ void KB(const float* __restrict__ W2, const float* __restrict__ b2,
                   const float* __restrict__ emb, const float* __restrict__ asp){
  __shared__ float semb[32][257];
  __shared__ float ssq[32][33];
  __shared__ float sw[32][33];
  __shared__ float sS[32];
  __shared__ float st[H_MLP];
  int bid = blockIdx.x, t = threadIdx.x;          // 256 threads
  if (bid < 32){
    int b = bid;
    for (int i = t; i < H_MLP; i += 256) st[i] = g_t1[b*H_MLP + i];
    __syncthreads();
    float a = 0.f;
    #pragma unroll 4
    for (int k = 0; k < H_MLP; k++) a += st[k]*W2[k*D + t];
    g_gf[b*D + t] = fmaxf(a + b2[t], 0.f);
    return;
  }
  int n0 = (bid - 32)*32;
  #pragma unroll
  for (int i = t; i < 32*256; i += 256){
    int r = i >> 8, c = i & 255; int n = n0 + r;
    semb[r][c] = (n < NN) ? emb[n*D + c] : 0.f;
  }
  if (t < 32) sS[t] = 0.f;

  // ---- pass 1: logits ----
  int nloc = t & 31, bq = t >> 5;                 // 8 warps, 4 b each
  float acc[4];
  #pragma unroll
  for (int i = 0; i < 4; i++) acc[i] = 0.f;
  for (int dc = 0; dc < 8; dc++){
    __syncthreads();
    for (int i = t; i < 32*32; i += 256){
      int b = i >> 5, c = i & 31;
      ssq[b][c] = g_sq[b*D + dc*32 + c];
    }
    __syncthreads();
    #pragma unroll
    for (int c = 0; c < 32; c++){
      float e = semb[nloc][dc*32 + c];
      #pragma unroll
      for (int bb = 0; bb < 4; bb++) acc[bb] += e*ssq[bq*4 + bb][c];
    }
  }
  // ---- exp + block-local S (no max-shift: masked logits are O(1e-3)) ----
  int n = n0 + nloc;
  float c0 = g_c0;
  #pragma unroll
  for (int bb = 0; bb < 4; bb++){
    int b = bq*4 + bb;
    float w = 0.f;
    if (n < NN) w = __expf((acc[bb] + c0)*asp[b*NN + n]);
    sw[b][nloc] = w;
    float s = w;
    #pragma unroll
    for (int o = 16; o > 0; o >>= 1) s += __shfl_down_sync(0xffffffffu, s, o);
    if (nloc == 0) atomicAdd(&sS[b], s);
  }
  __syncthreads();

  // ---- pass 2: u_raw += w . emb ----
  int dl = t & 31, g = t >> 5;
  for (int dc = 0; dc < 8; dc++){
    float a[4];
    #pragma unroll
    for (int i = 0; i < 4; i++) a[i] = 0.f;
    #pragma unroll
    for (int j = 0; j < 32; j++){
      float e = semb[j][dc*32 + dl];
      #pragma unroll
      for (int bb = 0; bb < 4; bb++) a[bb] += sw[g*4 + bb][j]*e;
    }
    #pragma unroll
    for (int bb = 0; bb < 4; bb++)
      atomicAdd(&g_u[(g*4 + bb)*D + dc*32 + dl], a[bb]);
  }
  if (t < 32) atomicAdd(&g_S[t], sS[t]);
}

// ============ KC2: normalize + highway + pack {hw, gf}; zero g_u
__global__ void KC2(const float* __restrict__ ehr){
  int i = blockIdx.x*512 + threadIdx.x;           // 0..8191
  int b = i >> 8;
  float u  = g_u[i] / g_S[b];
  float gt = g_gate[i];
  float hw = g_state[i]*u*(1.f - gt) + ehr[i]*gt;
  g_hg[i] = make_float2(hw, g_gf[i]);
  g_u[i] = 0.f;
}

// ============ KE: dual GEMV + blend (157 blocks x 512 thr, 64 n/block)
__global__ void KE(const float* __restrict__ asp, const float* __restrict__ lvl,
                   const float* __restrict__ W_gl, const float* __restrict__ b_gl,
                   const float* __restrict__ W_lay,const float* __restrict__ b_lay,
                   float* __restrict__ out){
  __shared__ float2 sv[32][130];
  int t = threadIdx.x;                            // 512
  if (blockIdx.x == 0 && t < B) g_S[t] = 0.f;     // reset for next replay (no KE reads)
  int nloc = t & 63, bq = t >> 6;                 // 8 groups x 4 b
  int n = blockIdx.x*64 + nloc;
  float accL[4], accG[4];
  #pragma unroll
  for (int i = 0; i < 4; i++){ accL[i] = 0.f; accG[i] = 0.f; }
  for (int h = 0; h < 2; h++){
    for (int i = t; i < 32*128; i += 512){
      int b = i >> 7, c = i & 127;
      sv[b][c] = g_hg[b*D + h*128 + c];
    }
    __syncthreads();
    if (n < NN){
      #pragma unroll 4
      for (int c = 0; c < 128; c++){
        int d = h*128 + c;
        float wl = W_lay[d*NN + n];
        float wg = W_gl [d*NN + n];
        #pragma unroll
        for (int bb = 0; bb < 4; bb++){
          float2 v = sv[bq*4 + bb][c];
          accL[bb] += v.x*wl;
          accG[bb] += v.y*wg;
        }
      }
    }
    __syncthreads();
  }
  if (n < NN){
    float bl = b_lay[n], bg = b_gl[n], lm = lvl[n];
    #pragma unroll
    for (int bb = 0; bb < 4; bb++){
      int b = bq*4 + bb;
      float ll = sigmoidf_(accL[bb] + bl);
      float lg = sigmoidf_(accG[bb] + bg);
      out[b*NN + n] = ALPHA*ll*asp[b*NN + n] + (1.f - ALPHA)*lg*lm;
    }
  }
}

// ---------------- launch ----------------
extern "C" void kernel_launch(void* const* d_in, const int* in_sizes, int n_in,
                              void* d_out, int out_size){
  const float* ehr    = (const float*)d_in[0];
  const float* path   = (const float*)d_in[1];
  const float* asp    = (const float*)d_in[2];
  const float* lvl    = (const float*)d_in[3];
  const float* emb    = (const float*)d_in[4];
  const float* W_pf   = (const float*)d_in[5];
  const float* b_pf   = (const float*)d_in[6];
  const float* W_s1   = (const float*)d_in[7];
  const float* b_s1   = (const float*)d_in[8];
  const float* W_s2   = (const float*)d_in[9];
  const float* b_s2   = (const float*)d_in[10];
  const float* W_gate = (const float*)d_in[11];
  const float* b_gate = (const float*)d_in[12];
  const float* W1     = (const float*)d_in[13];
  const float* b1     = (const float*)d_in[14];
  const float* W2     = (const float*)d_in[15];
  const float* b2     = (const float*)d_in[16];
  const float* W_gl   = (const float*)d_in[17];
  const float* b_gl   = (const float*)d_in[18];
  const float* W_lay  = (const float*)d_in[19];
  const float* b_lay  = (const float*)d_in[20];
  float* out = (float*)d_out;

  KA <<<208, 256>>>(ehr, path, W_pf, W_gate, W1, W_s1, W_s2, b_s1, b_s2);
  KA2<<<32, 256>>>(b_pf, b_gate, b1);
  KB <<<345, 256>>>(W2, b2, emb, asp);
  KC2<<<16, 512>>>(ehr);
  KE <<<157, 512>>>(asp, lvl, W_gl, b_gl, W_lay, b_lay, out);
}